// round 1
// baseline (speedup 1.0000x reference)
#include <cuda_runtime.h>
#include <cstdint>

// Shapes (fixed by the benchmark)
#define B 4
#define L 2048
#define H 8
#define D 64
#define SK 40          // sample_k
#define U 40           // top-k queries kept
#define BH (B*H)       // 32
#define C (H*D)        // 512 columns for cumsum view

// Attention chunking
#define KCH 128        // keys per chunk in dense attention
#define NCHK (L/KCH)   // 16
#define PITCH 68       // smem row pitch (floats): conflict-free for float4 key-major and float2 d-major

// Cumsum chunking
#define NCH 64
#define CHUNK (L/NCH)  // 32

// -------- scratch (device globals; no allocation allowed) --------
__device__ float g_M[BH * L];
__device__ int   g_Mtop[BH * U];
__device__ float g_pm[BH * U * NCHK];
__device__ float g_pl[BH * U * NCHK];
__device__ float g_pacc[BH * U * NCHK * D];
__device__ float g_csum[B * NCH * C];

// ===================== Stage 1: sampled scores -> M =====================
// One warp per (b,h,q). Lane holds 2 of the 64 dims (float2).
__global__ void k_sample_scores(const float* __restrict__ Q,
                                const float* __restrict__ K,
                                const int*   __restrict__ idx)
{
    int gw = blockIdx.x * (blockDim.x >> 5) + (threadIdx.x >> 5);
    if (gw >= BH * L) return;
    int lane = threadIdx.x & 31;
    int bh = gw >> 11;            // gw / L
    int q  = gw & (L - 1);
    int b = bh >> 3, h = bh & 7;

    const float* qrow = Q + (((size_t)b * L + q) * H + h) * D;
    float2 qv = *(const float2*)(qrow + 2 * lane);

    float mx = -1e30f;
    float sm = 0.f;
    const int* irow = idx + q * SK;
    #pragma unroll 4
    for (int s = 0; s < SK; s++) {
        int ki = irow[s];
        const float* krow = K + (((size_t)b * L + ki) * H + h) * D;
        float2 kv = *(const float2*)(krow + 2 * lane);
        float part = qv.x * kv.x + qv.y * kv.y;
        #pragma unroll
        for (int o = 16; o; o >>= 1)
            part += __shfl_xor_sync(0xffffffffu, part, o);
        mx = fmaxf(mx, part);
        sm += part;
    }
    if (lane == 0)
        g_M[gw] = mx - sm * (1.0f / SK);
}

// ===================== Stage 2: top-U per (b,h) =====================
// Iterative argmax, ties -> lowest index (matches jax.lax.top_k).
__global__ void k_topk()
{
    __shared__ float sv[L];
    __shared__ float rv[256];
    __shared__ int   ri[256];
    int bh = blockIdx.x;
    int t = threadIdx.x;

    for (int i = t; i < L; i += 256) sv[i] = g_M[bh * L + i];
    __syncthreads();

    for (int r = 0; r < U; r++) {
        float bv = -1e38f; int bi = L;
        for (int i = t; i < L; i += 256) {
            float v = sv[i];
            if (v > bv || (v == bv && i < bi)) { bv = v; bi = i; }
        }
        rv[t] = bv; ri[t] = bi;
        __syncthreads();
        #pragma unroll
        for (int s = 128; s; s >>= 1) {
            if (t < s) {
                float v2 = rv[t + s]; int i2 = ri[t + s];
                if (v2 > rv[t] || (v2 == rv[t] && i2 < ri[t])) { rv[t] = v2; ri[t] = i2; }
            }
            __syncthreads();
        }
        if (t == 0) {
            g_Mtop[bh * U + r] = ri[0];
            sv[ri[0]] = -1e38f;
        }
        __syncthreads();
    }
}

// ===================== Stage 3: cumsum of V along L -> out =====================
// View V/out as [B][L][C] with C = H*D = 512. Three-pass chunked scan.
__global__ void k_cumsum_a(const float* __restrict__ V)
{
    int blk = blockIdx.x;          // 0 .. B*NCH-1
    int b = blk / NCH, ch = blk % NCH;
    int c = threadIdx.x;           // 512
    const float* base = V + ((size_t)b * L + ch * CHUNK) * C + c;
    float s = 0.f;
    #pragma unroll
    for (int l = 0; l < CHUNK; l++) s += base[(size_t)l * C];
    g_csum[((size_t)b * NCH + ch) * C + c] = s;
}

__global__ void k_cumsum_b()
{
    int b = blockIdx.x;
    int c = threadIdx.x;
    float run = 0.f;
    #pragma unroll
    for (int ch = 0; ch < NCH; ch++) {
        size_t i = ((size_t)b * NCH + ch) * C + c;
        float t = g_csum[i];
        g_csum[i] = run;
        run += t;
    }
}

__global__ void k_cumsum_c(const float* __restrict__ V, float* __restrict__ out)
{
    int blk = blockIdx.x;
    int b = blk / NCH, ch = blk % NCH;
    int c = threadIdx.x;
    float run = g_csum[((size_t)b * NCH + ch) * C + c];
    const float* vb = V   + ((size_t)b * L + ch * CHUNK) * C + c;
    float*       ob = out + ((size_t)b * L + ch * CHUNK) * C + c;
    #pragma unroll
    for (int l = 0; l < CHUNK; l++) {
        run += vb[(size_t)l * C];
        ob[(size_t)l * C] = run;
    }
}

// ===================== Stage 4: dense attention partials =====================
// Block = (b,h, key-chunk). 256 threads = 8 warps; warp handles 5 of the 40 queries.
// Streaming (flash) softmax over the 128-key chunk; partial (m, l, acc[64]) to global.
__global__ void k_attn_partial(const float* __restrict__ Q,
                               const float* __restrict__ K,
                               const float* __restrict__ V)
{
    extern __shared__ float smf[];
    float* Ks = smf;                       // KCH * PITCH
    float* Vs = Ks + KCH * PITCH;          // KCH * PITCH
    float* Qs = Vs + KCH * PITCH;          // U * D
    float* pb = Qs + U * D;                // 8 * 32
    int*   ps = (int*)(pb + 8 * 32);       // U

    int bh = blockIdx.x >> 4;
    int ch = blockIdx.x & 15;
    int b = bh >> 3, h = bh & 7;
    int t = threadIdx.x;
    int k0 = ch * KCH;

    // load K,V chunk (padded rows)
    for (int i = t; i < KCH * D; i += 256) {
        int r = i >> 6, d = i & 63;
        size_t g = (((size_t)b * L + (k0 + r)) * H + h) * D + d;
        Ks[r * PITCH + d] = K[g];
        Vs[r * PITCH + d] = V[g];
    }
    for (int i = t; i < U; i += 256) ps[i] = g_Mtop[bh * U + i];
    __syncthreads();
    for (int i = t; i < U * D; i += 256) {
        int u = i >> 6, d = i & 63;
        Qs[i] = Q[(((size_t)b * L + ps[u]) * H + h) * D + d];
    }
    __syncthreads();

    int w = t >> 5, lane = t & 31;

    for (int uu = 0; uu < 5; uu++) {
        int u = w * 5 + uu;
        int p = ps[u];
        float m = -1e30f, l = 0.f;
        float2 acc = make_float2(0.f, 0.f);   // d = 2*lane, 2*lane+1

        #pragma unroll
        for (int g = 0; g < KCH / 32; g++) {
            int kl = g * 32 + lane;
            int kk = k0 + kl;
            // score: full 64-dot in-lane (float4 smem reads)
            const float4* q4 = (const float4*)&Qs[u * D];
            const float4* k4 = (const float4*)&Ks[kl * PITCH];
            float s = 0.f;
            #pragma unroll
            for (int i = 0; i < 16; i++) {
                float4 a = q4[i], c = k4[i];
                s += a.x * c.x + a.y * c.y + a.z * c.z + a.w * c.w;
            }
            s *= 0.125f;                       // 1/sqrt(64)
            bool valid = (kk <= p);
            float sv = valid ? s : -1e30f;
            float gm = sv;
            #pragma unroll
            for (int o = 16; o; o >>= 1)
                gm = fmaxf(gm, __shfl_xor_sync(0xffffffffu, gm, o));
            float mnew = fmaxf(m, gm);
            float pv = valid ? __expf(s - mnew) : 0.f;
            float cf = __expf(m - mnew);       // 1 if both -1e30; 0 if m=-1e30,mnew finite
            float ls = pv;
            #pragma unroll
            for (int o = 16; o; o >>= 1)
                ls += __shfl_xor_sync(0xffffffffu, ls, o);
            l = l * cf + ls;

            pb[w * 32 + lane] = pv;
            __syncwarp();
            float2 sacc = make_float2(0.f, 0.f);
            #pragma unroll
            for (int k = 0; k < 32; k += 4) {
                float4 pk = *(const float4*)&pb[w * 32 + k];
                float2 v0 = *(const float2*)&Vs[(g * 32 + k + 0) * PITCH + 2 * lane];
                float2 v1 = *(const float2*)&Vs[(g * 32 + k + 1) * PITCH + 2 * lane];
                float2 v2 = *(const float2*)&Vs[(g * 32 + k + 2) * PITCH + 2 * lane];
                float2 v3 = *(const float2*)&Vs[(g * 32 + k + 3) * PITCH + 2 * lane];
                sacc.x += pk.x * v0.x + pk.y * v1.x + pk.z * v2.x + pk.w * v3.x;
                sacc.y += pk.x * v0.y + pk.y * v1.y + pk.z * v2.y + pk.w * v3.y;
            }
            acc.x = acc.x * cf + sacc.x;
            acc.y = acc.y * cf + sacc.y;
            m = mnew;
            __syncwarp();
        }

        int pi = (bh * U + u) * NCHK + ch;
        if (lane == 0) { g_pm[pi] = m; g_pl[pi] = l; }
        g_pacc[(size_t)pi * D + 2 * lane + 0] = acc.x;
        g_pacc[(size_t)pi * D + 2 * lane + 1] = acc.y;
    }
}

// ===================== Stage 5: combine partials, scatter rows =====================
__global__ void k_attn_reduce(float* __restrict__ out)
{
    int task = blockIdx.x * (blockDim.x >> 5) + (threadIdx.x >> 5);
    if (task >= BH * U) return;
    int lane = threadIdx.x & 31;
    int bh = task / U, u = task % U;
    int b = bh >> 3, h = bh & 7;

    float m = -1e30f;
    #pragma unroll
    for (int c = 0; c < NCHK; c++) m = fmaxf(m, g_pm[task * NCHK + c]);
    float Lsum = 0.f;
    float2 a = make_float2(0.f, 0.f);
    #pragma unroll
    for (int c = 0; c < NCHK; c++) {
        float wgt = __expf(g_pm[task * NCHK + c] - m);
        Lsum += g_pl[task * NCHK + c] * wgt;
        float2 pa = *(const float2*)&g_pacc[(size_t)(task * NCHK + c) * D + 2 * lane];
        a.x += pa.x * wgt;
        a.y += pa.y * wgt;
    }
    float inv = 1.0f / Lsum;
    int p = g_Mtop[bh * U + u];
    size_t o = (((size_t)b * L + p) * H + h) * D + 2 * lane;
    out[o + 0] = a.x * inv;
    out[o + 1] = a.y * inv;
}

// ===================== launch =====================
extern "C" void kernel_launch(void* const* d_in, const int* in_sizes, int n_in,
                              void* d_out, int out_size)
{
    const float* Q   = (const float*)d_in[0];
    const float* K   = (const float*)d_in[1];
    const float* V   = (const float*)d_in[2];
    const int*   idx = (const int*)d_in[3];
    float* out = (float*)d_out;

    const int smem_k4 = (KCH * PITCH * 2 + U * D + 8 * 32) * (int)sizeof(float) + U * (int)sizeof(int);
    cudaFuncSetAttribute(k_attn_partial, cudaFuncAttributeMaxDynamicSharedMemorySize, smem_k4);

    // Stage 1: M scores (65536 warps)
    k_sample_scores<<<(BH * L) / 4, 128>>>(Q, K, idx);
    // Stage 2: top-k
    k_topk<<<BH, 256>>>();
    // Stage 3: cumsum -> out
    k_cumsum_a<<<B * NCH, C>>>(V);
    k_cumsum_b<<<B, C>>>();
    k_cumsum_c<<<B * NCH, C>>>(V, out);
    // Stage 4: dense attention partials for top queries
    k_attn_partial<<<BH * NCHK, 256, smem_k4>>>(Q, K, V);
    // Stage 5: combine + scatter
    k_attn_reduce<<<(BH * U) / 8, 256>>>(out);
}

// round 2
// speedup vs baseline: 1.4649x; 1.4649x over previous
#include <cuda_runtime.h>
#include <cstdint>

// Shapes (fixed by the benchmark)
#define B 4
#define L 2048
#define H 8
#define D 64
#define SK 40          // sample_k
#define U 40           // top-k queries kept
#define BH (B*H)       // 32
#define C (H*D)        // 512 columns for cumsum view

// Attention chunking
#define KCH 128        // keys per chunk in dense attention
#define NCHK (L/KCH)   // 16
#define PKS 68         // Ks pitch (floats): conflict-free float4 key-major reads
#define PVS 66         // Vs pitch (floats): conflict-free float2 d-major reads

// Cumsum chunking
#define NCH 64
#define CHUNK (L/NCH)  // 32

// -------- scratch (device globals; no allocation allowed) --------
__device__ float g_M[BH * L];
__device__ int   g_Mtop[BH * U];
__device__ float g_pm[BH * U * NCHK];
__device__ float g_pl[BH * U * NCHK];
__device__ float g_pacc[BH * U * NCHK * D];
__device__ float g_csum[B * NCH * C];

// ===================== Stage 1: sampled scores -> M =====================
// Block per query q (2048 blocks, 256 threads). Thread t: b=t>>6, h=(t>>3)&7,
// dim-group g=t&7 (8 floats). Q row cached in registers; each sample is one
// fully coalesced 2KB gather of K[b, ki, :, :]; 8-lane butterfly reduce.
__global__ void __launch_bounds__(256) k_sample_scores(
    const float* __restrict__ Q,
    const float* __restrict__ K,
    const int*   __restrict__ idx)
{
    __shared__ int sidx[SK];
    int q = blockIdx.x;
    int t = threadIdx.x;
    int b = t >> 6;
    int h = (t >> 3) & 7;
    int g = t & 7;

    if (t < SK) sidx[t] = idx[q * SK + t];
    __syncthreads();

    const float* qp = Q + (((size_t)b * L + q) * H + h) * D + g * 8;
    float4 qa = *(const float4*)qp;
    float4 qb = *(const float4*)(qp + 4);

    float mx = -1e30f, sm = 0.f;
    const size_t hoff = (size_t)h * D + (size_t)g * 8;
    #pragma unroll 4
    for (int s = 0; s < SK; s++) {
        const float* kp = K + ((size_t)b * L + sidx[s]) * (H * D) + hoff;
        float4 ka = *(const float4*)kp;
        float4 kb = *(const float4*)(kp + 4);
        float d = qa.x * ka.x + qa.y * ka.y + qa.z * ka.z + qa.w * ka.w
                + qb.x * kb.x + qb.y * kb.y + qb.z * kb.z + qb.w * kb.w;
        d += __shfl_xor_sync(0xffffffffu, d, 1);
        d += __shfl_xor_sync(0xffffffffu, d, 2);
        d += __shfl_xor_sync(0xffffffffu, d, 4);
        mx = fmaxf(mx, d);
        sm += d;
    }
    if (g == 0)
        g_M[(t >> 3) * L + q] = mx - sm * (1.0f / SK);
}

// ===================== Stage 2: top-U per (b,h) =====================
// Iterative argmax, ties -> lowest index (matches jax.lax.top_k).
__global__ void k_topk()
{
    __shared__ float sv[L];
    __shared__ float rv[256];
    __shared__ int   ri[256];
    int bh = blockIdx.x;
    int t = threadIdx.x;

    for (int i = t; i < L; i += 256) sv[i] = g_M[bh * L + i];
    __syncthreads();

    for (int r = 0; r < U; r++) {
        float bv = -1e38f; int bi = L;
        for (int i = t; i < L; i += 256) {
            float v = sv[i];
            if (v > bv || (v == bv && i < bi)) { bv = v; bi = i; }
        }
        rv[t] = bv; ri[t] = bi;
        __syncthreads();
        #pragma unroll
        for (int s = 128; s; s >>= 1) {
            if (t < s) {
                float v2 = rv[t + s]; int i2 = ri[t + s];
                if (v2 > rv[t] || (v2 == rv[t] && i2 < ri[t])) { rv[t] = v2; ri[t] = i2; }
            }
            __syncthreads();
        }
        if (t == 0) {
            g_Mtop[bh * U + r] = ri[0];
            sv[ri[0]] = -1e38f;
        }
        __syncthreads();
    }
}

// ===================== Stage 3: cumsum of V along L -> out =====================
// View V/out as [B][L][C], C = 512. Pass A: chunk sums. Pass C: each block
// computes its own prefix from the (L2-resident) chunk sums, then scans.
__global__ void k_cumsum_a(const float* __restrict__ V)
{
    int blk = blockIdx.x;          // 0 .. B*NCH-1
    int b = blk / NCH, ch = blk % NCH;
    int c = threadIdx.x;           // 512
    const float* base = V + ((size_t)b * L + ch * CHUNK) * C + c;
    float s = 0.f;
    #pragma unroll
    for (int l = 0; l < CHUNK; l++) s += base[(size_t)l * C];
    g_csum[((size_t)b * NCH + ch) * C + c] = s;
}

__global__ void k_cumsum_c(const float* __restrict__ V, float* __restrict__ out)
{
    int blk = blockIdx.x;
    int b = blk / NCH, ch = blk % NCH;
    int c = threadIdx.x;
    float run = 0.f;
    for (int j = 0; j < ch; j++)
        run += g_csum[((size_t)b * NCH + j) * C + c];
    const float* vb = V   + ((size_t)b * L + ch * CHUNK) * C + c;
    float*       ob = out + ((size_t)b * L + ch * CHUNK) * C + c;
    #pragma unroll
    for (int l = 0; l < CHUNK; l++) {
        run += vb[(size_t)l * C];
        ob[(size_t)l * C] = run;
    }
}

// ===================== Stage 4: dense attention partials =====================
// Block = (b,h, key-chunk). 8 warps; each warp owns 5 of the 40 queries.
// Scores: K float4 shared across the warp's 5 queries, scores in registers.
// Whole 128-key chunk softmaxed at once (no online rescale inside chunk).
// AV: V float2 shared across the 5 queries via smem-staged p (broadcast reads).
__global__ void __launch_bounds__(256) k_attn_partial(
    const float* __restrict__ Q,
    const float* __restrict__ K,
    const float* __restrict__ V)
{
    extern __shared__ float smf[];
    float* Ks = smf;                       // KCH * PKS
    float* Vs = Ks + KCH * PKS;            // KCH * PVS
    float* Qs = Vs + KCH * PVS;            // U * D
    float* pb = Qs + U * D;                // 8 warps * 5 q * 128 k
    int*   ps = (int*)(pb + 8 * 5 * KCH);  // U

    int bh = blockIdx.x >> 4;
    int ch = blockIdx.x & 15;
    int b = bh >> 3, h = bh & 7;
    int t = threadIdx.x;
    int k0 = ch * KCH;

    // Load K,V chunk (global coalesced along d; STS consecutive -> conflict-free)
    for (int i = t; i < KCH * D; i += 256) {
        int r = i >> 6, d = i & 63;
        size_t gidx = (((size_t)b * L + (k0 + r)) * H + h) * D + d;
        Ks[r * PKS + d] = K[gidx];
        Vs[r * PVS + d] = V[gidx];
    }
    if (t < U) ps[t] = g_Mtop[bh * U + t];
    __syncthreads();
    for (int i = t; i < U * D; i += 256) {
        int u = i >> 6, d = i & 63;
        Qs[i] = Q[(((size_t)b * L + ps[u]) * H + h) * D + d];
    }
    __syncthreads();

    int w = t >> 5, lane = t & 31;
    const float4* Qb = (const float4*)Qs;

    // ---- scores: lane covers keys {g*32+lane : g<4}; 5 q accumulators each ----
    float s4[5][4];
    #pragma unroll
    for (int q = 0; q < 5; q++)
        #pragma unroll
        for (int g = 0; g < 4; g++) s4[q][g] = 0.f;

    #pragma unroll 4
    for (int i = 0; i < 16; i++) {
        float4 kk[4];
        #pragma unroll
        for (int g = 0; g < 4; g++)
            kk[g] = *(const float4*)&Ks[(g * 32 + lane) * PKS + 4 * i];
        #pragma unroll
        for (int q = 0; q < 5; q++) {
            float4 qv = Qb[(w * 5 + q) * 16 + i];
            #pragma unroll
            for (int g = 0; g < 4; g++)
                s4[q][g] += qv.x * kk[g].x + qv.y * kk[g].y
                          + qv.z * kk[g].z + qv.w * kk[g].w;
        }
    }

    // ---- per-q softmax over the 128-key chunk; stage p in smem ----
    #pragma unroll
    for (int q = 0; q < 5; q++) {
        int u = w * 5 + q;
        int p = ps[u];
        float sc[4]; bool ok[4];
        float m = -1e30f;
        #pragma unroll
        for (int g = 0; g < 4; g++) {
            sc[g] = s4[q][g] * 0.125f;             // 1/sqrt(64)
            ok[g] = (k0 + g * 32 + lane) <= p;
            m = fmaxf(m, ok[g] ? sc[g] : -1e30f);
        }
        #pragma unroll
        for (int o = 16; o; o >>= 1)
            m = fmaxf(m, __shfl_xor_sync(0xffffffffu, m, o));
        float l = 0.f;
        #pragma unroll
        for (int g = 0; g < 4; g++) {
            float pv = ok[g] ? __expf(sc[g] - m) : 0.f;
            l += pv;
            pb[w * (5 * KCH) + q * KCH + g * 32 + lane] = pv;
        }
        #pragma unroll
        for (int o = 16; o; o >>= 1)
            l += __shfl_xor_sync(0xffffffffu, l, o);
        if (lane == 0) {
            int pi = (bh * U + u) * NCHK + ch;
            g_pm[pi] = m;
            g_pl[pi] = l;
        }
    }
    __syncwarp();

    // ---- AV: lane owns dims {2*lane, 2*lane+1}; V shared across 5 queries ----
    float2 acc[5];
    #pragma unroll
    for (int q = 0; q < 5; q++) acc[q] = make_float2(0.f, 0.f);

    #pragma unroll 4
    for (int k = 0; k < KCH; k += 4) {
        float2 v0 = *(const float2*)&Vs[(k + 0) * PVS + 2 * lane];
        float2 v1 = *(const float2*)&Vs[(k + 1) * PVS + 2 * lane];
        float2 v2 = *(const float2*)&Vs[(k + 2) * PVS + 2 * lane];
        float2 v3 = *(const float2*)&Vs[(k + 3) * PVS + 2 * lane];
        #pragma unroll
        for (int q = 0; q < 5; q++) {
            float4 pq = *(const float4*)&pb[w * (5 * KCH) + q * KCH + k];
            acc[q].x += pq.x * v0.x + pq.y * v1.x + pq.z * v2.x + pq.w * v3.x;
            acc[q].y += pq.x * v0.y + pq.y * v1.y + pq.z * v2.y + pq.w * v3.y;
        }
    }

    #pragma unroll
    for (int q = 0; q < 5; q++) {
        int u = w * 5 + q;
        int pi = (bh * U + u) * NCHK + ch;
        *(float2*)&g_pacc[(size_t)pi * D + 2 * lane] = acc[q];
    }
}

// ===================== Stage 5: combine partials, scatter rows =====================
__global__ void k_attn_reduce(float* __restrict__ out)
{
    int task = blockIdx.x * (blockDim.x >> 5) + (threadIdx.x >> 5);
    if (task >= BH * U) return;
    int lane = threadIdx.x & 31;
    int bh = task / U, u = task % U;
    int b = bh >> 3, h = bh & 7;

    float m = -1e30f;
    #pragma unroll
    for (int c = 0; c < NCHK; c++) m = fmaxf(m, g_pm[task * NCHK + c]);
    float Lsum = 0.f;
    float2 a = make_float2(0.f, 0.f);
    #pragma unroll
    for (int c = 0; c < NCHK; c++) {
        float wgt = __expf(g_pm[task * NCHK + c] - m);
        Lsum += g_pl[task * NCHK + c] * wgt;
        float2 pa = *(const float2*)&g_pacc[(size_t)(task * NCHK + c) * D + 2 * lane];
        a.x += pa.x * wgt;
        a.y += pa.y * wgt;
    }
    float inv = 1.0f / Lsum;
    int p = g_Mtop[bh * U + u];
    size_t o = (((size_t)b * L + p) * H + h) * D + 2 * lane;
    out[o + 0] = a.x * inv;
    out[o + 1] = a.y * inv;
}

// ===================== launch =====================
extern "C" void kernel_launch(void* const* d_in, const int* in_sizes, int n_in,
                              void* d_out, int out_size)
{
    const float* Q   = (const float*)d_in[0];
    const float* K   = (const float*)d_in[1];
    const float* V   = (const float*)d_in[2];
    const int*   idx = (const int*)d_in[3];
    float* out = (float*)d_out;

    const int smem_k4 = (KCH * PKS + KCH * PVS + U * D + 8 * 5 * KCH) * (int)sizeof(float)
                      + U * (int)sizeof(int);
    cudaFuncSetAttribute(k_attn_partial, cudaFuncAttributeMaxDynamicSharedMemorySize, smem_k4);

    // Stage 1: M scores (block per query)
    k_sample_scores<<<L, 256>>>(Q, K, idx);
    // Stage 2: top-k
    k_topk<<<BH, 256>>>();
    // Stage 3: cumsum -> out
    k_cumsum_a<<<B * NCH, C>>>(V);
    k_cumsum_c<<<B * NCH, C>>>(V, out);
    // Stage 4: dense attention partials for top queries
    k_attn_partial<<<BH * NCHK, 256, smem_k4>>>(Q, K, V);
    // Stage 5: combine + scatter
    k_attn_reduce<<<(BH * U) / 8, 256>>>(out);
}